// round 7
// baseline (speedup 1.0000x reference)
#include <cuda_runtime.h>
#include <cuda_fp16.h>
#include <cstdint>

#define BATCH 512
#define INC   1152
#define NC    10
#define DC    16
#define JD    160      // NC*DC
#define NSLOT 80       // half2 slots per (b,i): slot m holds jd {2m, 2m+1}
#define CSZ   4        // cluster CTAs per batch
#define IQ    288      // i-range per route CTA (INC / CSZ)
#define RW    12       // warps per route CTA (384 threads)
#define EPSQ  1e-7f

typedef unsigned long long u64;

// u_hat in fp16, layout [b][i][slot], slot m = jd pair (2m, 2m+1). 188 MB.
__device__ __half2 g_uhat[(size_t)BATCH * INC * NSLOT];

// ---------------------------------------------------------------------------
// helpers
// ---------------------------------------------------------------------------
__device__ __forceinline__ void cluster_sync() {
    asm volatile("barrier.cluster.arrive.aligned;\n\t"
                 "barrier.cluster.wait.aligned;" ::: "memory");
}

__device__ __forceinline__ float peer_f32(const float* p, unsigned int peer) {
    unsigned int a = (unsigned int)__cvta_generic_to_shared(p);
    unsigned int r;
    asm("mapa.shared::cluster.u32 %0, %1, %2;" : "=r"(r) : "r"(a), "r"(peer));
    float v;
    asm volatile("ld.shared::cluster.f32 %0, [%1];" : "=f"(v) : "r"(r));
    return v;
}

__device__ __forceinline__ u64 pack2(float lo, float hi) {
    u64 r;
    asm("mov.b64 %0, {%1, %2};" : "=l"(r) : "f"(lo), "f"(hi));
    return r;
}
__device__ __forceinline__ void fma2(u64& d, u64 a, u64 b) {
    asm("fma.rn.f32x2 %0, %1, %2, %0;" : "+l"(d) : "l"(a), "l"(b));
}
__device__ __forceinline__ void add2(u64& d, u64 a) {
    asm("add.rn.f32x2 %0, %0, %1;" : "+l"(d) : "l"(a));
}
// f32x2 {lo,hi} -> half2 {.x=lo, .y=hi}
__device__ __forceinline__ __half2 f2_to_h2(u64 v) {
    float lo, hi;
    asm("mov.b64 {%0, %1}, %2;" : "=f"(lo), "=f"(hi) : "l"(v));
    unsigned int r;
    asm("cvt.rn.f16x2.f32 %0, %1, %2;" : "=r"(r) : "f"(hi), "f"(lo));
    return *(__half2*)&r;
}
union F2U { float2 f; u64 u; };

__device__ __forceinline__ u64 h2_to_u64f2(__half2 h) {
    F2U t;
    t.f = __half22float2(h);
    return t.u;
}

// ---------------------------------------------------------------------------
// Kernel A: u_hat[b,i,jd] = sum_k inputs[b,i,k] * W[jd(i),k], fp16 output.
// Warp owns (i, 64-batch chunk); W pairs packed as f32x2 in registers;
// FFMA2 halves the FMA instruction count; unroll 4 batches independent LDGs.
// ---------------------------------------------------------------------------
__global__ __launch_bounds__(256) void uhat_kernel(const float* __restrict__ inp,
                                                   const float* __restrict__ W) {
    const int warp = threadIdx.x >> 5;
    const int lane = threadIdx.x & 31;
    const int gw = blockIdx.x * 8 + warp;   // [0, 9216)
    const int i = gw >> 3;
    const int chunk = gw & 7;

    // wp?[k] = pack(W[jd0][k], W[jd0+1][k])
    u64 wpA[8], wpB[8], wpC[8];
#define LOADW(dst, jd0)                                                        \
    {                                                                          \
        const int j_ = (jd0) >> 4, d_ = (jd0) & 15;                            \
        const float4* p_ =                                                     \
            (const float4*)(W + (((size_t)j_ * INC + i) * DC + d_) * 8);       \
        float4 q0 = __ldg(p_), q1 = __ldg(p_ + 1), q2 = __ldg(p_ + 2),         \
               q3 = __ldg(p_ + 3);                                             \
        dst[0] = pack2(q0.x, q2.x); dst[1] = pack2(q0.y, q2.y);                \
        dst[2] = pack2(q0.z, q2.z); dst[3] = pack2(q0.w, q2.w);                \
        dst[4] = pack2(q1.x, q3.x); dst[5] = pack2(q1.y, q3.y);                \
        dst[6] = pack2(q1.z, q3.z); dst[7] = pack2(q1.w, q3.w);                \
    }
    LOADW(wpA, 2 * lane);
    LOADW(wpB, 64 + 2 * lane);
    if (lane < 16) {
        LOADW(wpC, 128 + 2 * lane);
    } else {
#pragma unroll
        for (int k = 0; k < 8; k++) wpC[k] = 0ull;
    }
#undef LOADW

    const int b0 = chunk * 64;
#pragma unroll 4
    for (int bb = 0; bb < 64; bb++) {
        const int b = b0 + bb;
        const float4* ip = (const float4*)(inp + ((size_t)b * INC + i) * 8);
        float4 x = __ldg(ip), y = __ldg(ip + 1);

        u64 in2[8];
        in2[0] = pack2(x.x, x.x); in2[1] = pack2(x.y, x.y);
        in2[2] = pack2(x.z, x.z); in2[3] = pack2(x.w, x.w);
        in2[4] = pack2(y.x, y.x); in2[5] = pack2(y.y, y.y);
        in2[6] = pack2(y.z, y.z); in2[7] = pack2(y.w, y.w);

        u64 aA = 0ull, aB = 0ull, aC = 0ull;
#pragma unroll
        for (int k = 0; k < 8; k++) {
            fma2(aA, in2[k], wpA[k]);
            fma2(aB, in2[k], wpB[k]);
            fma2(aC, in2[k], wpC[k]);
        }
        __half2* up = g_uhat + ((size_t)b * INC + i) * NSLOT;
        up[lane] = f2_to_h2(aA);
        up[32 + lane] = f2_to_h2(aB);
        if (lane < 16) up[64 + lane] = f2_to_h2(aC);
    }
}

// ---------------------------------------------------------------------------
// Kernel R: routing. Cluster of 4 CTAs per batch; each CTA caches its 288-i
// quarter of u_hat[b] in smem (92 KB fp16) while accumulating pass-0's uniform
// sum, then runs passes 1,2 from smem. ~100 KB smem -> 2 CTAs/SM (24 warps).
// Lane layout: lanes 0..19 active, lane l owns half2 slots 4l..4l+3 (16B),
// all within j = l>>1; pair-shuffle(xor 1) completes the d-dot.
// Dot computed in fp16 (HFMA2, no converts); s accumulated in fp32 (FFMA2).
// ---------------------------------------------------------------------------
__global__ __launch_bounds__(384, 2) __cluster_dims__(CSZ, 1, 1)
void route_kernel(float* __restrict__ out) {
    extern __shared__ char smraw[];
    __half2* Usm = (__half2*)smraw;                            // IQ*80 half2
    float* red = (float*)(smraw + (size_t)IQ * NSLOT * 4);     // RW*160
    float* sfin = red + RW * JD;                               // 160 (DSMEM)
    float* stot = sfin + JD;                                   // 160
    float* Vsm = stot + JD;                                    // 160
    __half2* Vh2 = (__half2*)(Vsm + JD);                       // 80 half2
    float* scl = (float*)(Vh2 + NSLOT);                        // 16

    const int tid = threadIdx.x;
    const int warp = tid >> 5;
    const int lane = tid & 31;
    const int b = blockIdx.x >> 2;
    const unsigned int rank = blockIdx.x & 3;
    const bool act = (lane < 20);
    const int sl = act ? 4 * lane : 0;
    float2* red2 = (float2*)red;

    const __half2* gsrc = g_uhat + ((size_t)b * INC + rank * IQ) * NSLOT;

    // ---- stream u_hat quarter -> smem, accumulate pass-0 (c = 0.1) ----
    u64 a0 = 0ull, a1 = 0ull, a2 = 0ull, a3 = 0ull;
    if (act) {
#pragma unroll 2
        for (int i = warp; i < IQ; i += RW) {
            uint4 u = *(const uint4*)(gsrc + (size_t)i * NSLOT + sl);
            *(uint4*)(Usm + (size_t)i * NSLOT + sl) = u;
            add2(a0, h2_to_u64f2(*(__half2*)&u.x));
            add2(a1, h2_to_u64f2(*(__half2*)&u.y));
            add2(a2, h2_to_u64f2(*(__half2*)&u.z));
            add2(a3, h2_to_u64f2(*(__half2*)&u.w));
        }
        F2U t0, t1, t2, t3;
        t0.u = a0; t1.u = a1; t2.u = a2; t3.u = a3;
        red2[warp * 80 + sl + 0] = t0.f;
        red2[warp * 80 + sl + 1] = t1.f;
        red2[warp * 80 + sl + 2] = t2.f;
        red2[warp * 80 + sl + 3] = t3.f;
    }
    __syncthreads();
    if (tid < JD) {
        float s = 0.f;
#pragma unroll
        for (int w = 0; w < RW; w++) s += red[w * JD + tid];
        sfin[tid] = s;
    }
    __syncthreads();
    cluster_sync();
    if (tid < JD) {
        float s = sfin[tid];
#pragma unroll
        for (unsigned int r = 1; r < CSZ; r++)
            s += peer_f32(sfin + tid, rank ^ r);
        stot[tid] = 0.1f * s;
    }
    __syncthreads();
    if (tid < NC) {
        float sq = 0.f;
#pragma unroll
        for (int d = 0; d < DC; d++) {
            float v = stot[tid * DC + d];
            sq = fmaf(v, v, sq);
        }
        scl[tid] = sq / ((1.0f + sq) * sqrtf(sq + EPSQ));
    }
    __syncthreads();
    if (tid < NSLOT) {  // V in f32 (Vsm) and as half2 pairs (Vh2) for the dot
        float sc = scl[tid >> 3];
        float va = sc * stot[2 * tid];
        float vb = sc * stot[2 * tid + 1];
        Vsm[2 * tid] = va;
        Vsm[2 * tid + 1] = vb;
        Vh2[tid] = __floats2half2_rn(va, vb);
    }
    __syncthreads();
    cluster_sync();  // peers done reading sfin; Vsm/Vh2 ready

    // ---- passes 1,2 from smem ----
    for (int p = 1; p <= 2; p++) {
        uint4 vraw = *(const uint4*)(Vh2 + sl);
        __half2 v0 = *(__half2*)&vraw.x, v1 = *(__half2*)&vraw.y;
        __half2 v2 = *(__half2*)&vraw.z, v3 = *(__half2*)&vraw.w;
        u64 s0 = 0ull, s1 = 0ull, s2 = 0ull, s3 = 0ull;
#pragma unroll 4
        for (int i = warp; i < IQ; i += RW) {
            uint4 u = *(const uint4*)(Usm + (size_t)i * NSLOT + sl);
            __half2 h0 = *(__half2*)&u.x, h1 = *(__half2*)&u.y;
            __half2 h2 = *(__half2*)&u.z, h3 = *(__half2*)&u.w;

            // dot in fp16: 4 HFMA2, no converts
            __half2 th = __hmul2(h0, v0);
            th = __hfma2(h1, v1, th);
            th = __hfma2(h2, v2, th);
            th = __hfma2(h3, v3, th);
            float2 tf = __half22float2(th);
            float t = tf.x + tf.y;
            t += __shfl_xor_sync(0xffffffffu, t, 1);  // full dot, j = lane>>1

            // |t| < ~4 -> no max-subtraction needed
            float e = act ? __expf(t) : 0.f;
            float sv = e;
            sv += __shfl_xor_sync(0xffffffffu, sv, 2);
            sv += __shfl_xor_sync(0xffffffffu, sv, 4);
            sv += __shfl_xor_sync(0xffffffffu, sv, 8);
            sv += __shfl_xor_sync(0xffffffffu, sv, 16);  // = sum_j e_j exactly
            float cf = e * __fdividef(1.f, sv);
            u64 cc = pack2(cf, cf);

            // accumulate in fp32 pairs (FFMA2)
            fma2(s0, h2_to_u64f2(h0), cc);
            fma2(s1, h2_to_u64f2(h1), cc);
            fma2(s2, h2_to_u64f2(h2), cc);
            fma2(s3, h2_to_u64f2(h3), cc);
        }
        if (act) {
            F2U t0, t1, t2, t3;
            t0.u = s0; t1.u = s1; t2.u = s2; t3.u = s3;
            red2[warp * 80 + sl + 0] = t0.f;
            red2[warp * 80 + sl + 1] = t1.f;
            red2[warp * 80 + sl + 2] = t2.f;
            red2[warp * 80 + sl + 3] = t3.f;
        }
        __syncthreads();
        if (tid < JD) {
            float s = 0.f;
#pragma unroll
            for (int w = 0; w < RW; w++) s += red[w * JD + tid];
            sfin[tid] = s;
        }
        __syncthreads();
        cluster_sync();
        if (tid < JD) {
            float s = sfin[tid];
#pragma unroll
            for (unsigned int r = 1; r < CSZ; r++)
                s += peer_f32(sfin + tid, rank ^ r);
            stot[tid] = s;
        }
        __syncthreads();
        if (tid < NC) {
            float sq = 0.f;
#pragma unroll
            for (int d = 0; d < DC; d++) {
                float v = stot[tid * DC + d];
                sq = fmaf(v, v, sq);
            }
            scl[tid] = sq / ((1.0f + sq) * sqrtf(sq + EPSQ));
        }
        __syncthreads();
        if (p == 1) {
            if (tid < NSLOT) {  // V += v; refresh Vh2
                float sc = scl[tid >> 3];
                float va = Vsm[2 * tid] + sc * stot[2 * tid];
                float vb = Vsm[2 * tid + 1] + sc * stot[2 * tid + 1];
                Vsm[2 * tid] = va;
                Vsm[2 * tid + 1] = vb;
                Vh2[tid] = __floats2half2_rn(va, vb);
            }
            __syncthreads();
        } else {
            if (rank == 0 && tid < JD)
                out[(size_t)b * JD + tid] = scl[tid >> 4] * stot[tid];
        }
        cluster_sync();  // sfin reuse / exit safety
    }
}

// ---------------------------------------------------------------------------
extern "C" void kernel_launch(void* const* d_in, const int* in_sizes, int n_in,
                              void* d_out, int out_size) {
    const float* inputs = (const float*)d_in[0];  // [512, 1152, 8]
    const float* W = (const float*)d_in[1];       // [10, 1152, 16, 8]
    float* out = (float*)d_out;                   // [512, 10, 16]

    uhat_kernel<<<INC, 256>>>(inputs, W);

    const int smem =
        IQ * NSLOT * 4 + (RW * JD + 3 * JD) * 4 + NSLOT * 4 + NC * 4;  // ~100 KB
    cudaFuncSetAttribute(route_kernel,
                         cudaFuncAttributeMaxDynamicSharedMemorySize, smem);
    route_kernel<<<BATCH * CSZ, 384, smem>>>(out);
}

// round 8
// speedup vs baseline: 1.0296x; 1.0296x over previous
#include <cuda_runtime.h>
#include <cuda_fp16.h>
#include <cstdint>

#define BATCH 512
#define INC   1152
#define NC    10
#define DC    16
#define JD    160      // NC*DC
#define NSLOT 80       // half2 slots per (b,i): slot m holds jd {2m, 2m+1}
#define CSZ   4        // cluster CTAs per batch
#define IQ    288      // i-range per route CTA (INC / CSZ)
#define RW    12       // warps per route CTA (384 threads)
#define EPSQ  1e-7f

typedef unsigned long long u64;

// u_hat in fp16, layout [b][i][slot], slot m = jd pair (2m, 2m+1). 188 MB.
__device__ __half2 g_uhat[(size_t)BATCH * INC * NSLOT];

// ---------------------------------------------------------------------------
// helpers
// ---------------------------------------------------------------------------
__device__ __forceinline__ void cluster_sync() {
    asm volatile("barrier.cluster.arrive.aligned;\n\t"
                 "barrier.cluster.wait.aligned;" ::: "memory");
}

__device__ __forceinline__ float peer_f32(const float* p, unsigned int peer) {
    unsigned int a = (unsigned int)__cvta_generic_to_shared(p);
    unsigned int r;
    asm("mapa.shared::cluster.u32 %0, %1, %2;" : "=r"(r) : "r"(a), "r"(peer));
    float v;
    asm volatile("ld.shared::cluster.f32 %0, [%1];" : "=f"(v) : "r"(r));
    return v;
}

__device__ __forceinline__ u64 pack2(float lo, float hi) {
    u64 r;
    asm("mov.b64 %0, {%1, %2};" : "=l"(r) : "f"(lo), "f"(hi));
    return r;
}
__device__ __forceinline__ void fma2(u64& d, u64 a, u64 b) {
    asm("fma.rn.f32x2 %0, %1, %2, %3;" : "=l"(d) : "l"(a), "l"(b), "l"(d));
}
__device__ __forceinline__ void add2(u64& d, u64 a) {
    asm("add.rn.f32x2 %0, %0, %1;" : "+l"(d) : "l"(a));
}
// f32x2 {lo,hi} -> half2 {.x=lo, .y=hi}
__device__ __forceinline__ __half2 f2_to_h2(u64 v) {
    float lo, hi;
    asm("mov.b64 {%0, %1}, %2;" : "=f"(lo), "=f"(hi) : "l"(v));
    unsigned int r;
    asm("cvt.rn.f16x2.f32 %0, %1, %2;" : "=r"(r) : "f"(hi), "f"(lo));
    return *(__half2*)&r;
}
union F2U { float2 f; u64 u; };

__device__ __forceinline__ u64 h2_to_u64f2(__half2 h) {
    F2U t;
    t.f = __half22float2(h);
    return t.u;
}

// ---------------------------------------------------------------------------
// Kernel A: u_hat[b,i,jd] = sum_k inputs[b,i,k] * W[jd(i),k], fp16 output.
// Exact R6 configuration (82 us): FFMA2 + 1-deep input prefetch, unroll 2.
// ---------------------------------------------------------------------------
__global__ __launch_bounds__(256) void uhat_kernel(const float* __restrict__ inp,
                                                   const float* __restrict__ W) {
    const int warp = threadIdx.x >> 5;
    const int lane = threadIdx.x & 31;
    const int gw = blockIdx.x * 8 + warp;   // [0, 9216)
    const int i = gw >> 3;
    const int chunk = gw & 7;

    // wp?[k] = pack(W[jd0][k], W[jd0+1][k])
    u64 wpA[8], wpB[8], wpC[8];
#define LOADW(dst, jd0)                                                        \
    {                                                                          \
        const int j_ = (jd0) >> 4, d_ = (jd0) & 15;                            \
        const float4* p_ =                                                     \
            (const float4*)(W + (((size_t)j_ * INC + i) * DC + d_) * 8);       \
        float4 q0 = __ldg(p_), q1 = __ldg(p_ + 1), q2 = __ldg(p_ + 2),         \
               q3 = __ldg(p_ + 3);                                             \
        dst[0] = pack2(q0.x, q2.x); dst[1] = pack2(q0.y, q2.y);                \
        dst[2] = pack2(q0.z, q2.z); dst[3] = pack2(q0.w, q2.w);                \
        dst[4] = pack2(q1.x, q3.x); dst[5] = pack2(q1.y, q3.y);                \
        dst[6] = pack2(q1.z, q3.z); dst[7] = pack2(q1.w, q3.w);                \
    }
    LOADW(wpA, 2 * lane);
    LOADW(wpB, 64 + 2 * lane);
    if (lane < 16) {
        LOADW(wpC, 128 + 2 * lane);
    } else {
#pragma unroll
        for (int k = 0; k < 8; k++) wpC[k] = 0ull;
    }
#undef LOADW

    const int b0 = chunk * 64;
    const float4* ip0 = (const float4*)(inp + ((size_t)b0 * INC + i) * 8);
    float4 x = __ldg(ip0), y = __ldg(ip0 + 1);
#pragma unroll 2
    for (int bb = 0; bb < 64; bb++) {
        u64 in2[8];
        in2[0] = pack2(x.x, x.x); in2[1] = pack2(x.y, x.y);
        in2[2] = pack2(x.z, x.z); in2[3] = pack2(x.w, x.w);
        in2[4] = pack2(y.x, y.x); in2[5] = pack2(y.y, y.y);
        in2[6] = pack2(y.z, y.z); in2[7] = pack2(y.w, y.w);
        if (bb + 1 < 64) {  // prefetch next batch's inputs
            const float4* ipn =
                (const float4*)(inp + ((size_t)(b0 + bb + 1) * INC + i) * 8);
            x = __ldg(ipn);
            y = __ldg(ipn + 1);
        }

        u64 aA = 0ull, aB = 0ull, aC = 0ull;
#pragma unroll
        for (int k = 0; k < 8; k++) {
            fma2(aA, in2[k], wpA[k]);
            fma2(aB, in2[k], wpB[k]);
            fma2(aC, in2[k], wpC[k]);
        }
        __half2* up = g_uhat + ((size_t)(b0 + bb) * INC + i) * NSLOT;
        up[lane] = f2_to_h2(aA);
        up[32 + lane] = f2_to_h2(aB);
        if (lane < 16) up[64 + lane] = f2_to_h2(aC);
    }
}

// ---------------------------------------------------------------------------
// Kernel R: routing. Cluster of 4 CTAs per batch; u_hat quarter cached in
// smem. Each pass runs 3 shuffle-free stages:
//   A: lane=(i_off,j) computes full fp16 dot t[i,j], stores e=exp(t) (fp16)
//   B: thread-per-i stores w[i] = 1/sum_j e[i,j]
//   C: lane l<20 accumulates s += (e[i,j]*w[i]) * u[i,slot] with broadcast
//      smem loads (i uniform across the warp) -- no shuffles anywhere.
// ---------------------------------------------------------------------------
__global__ __launch_bounds__(384, 2) __cluster_dims__(CSZ, 1, 1)
void route_kernel(float* __restrict__ out) {
    extern __shared__ char smraw[];
    __half2* Usm = (__half2*)smraw;                            // 92160 B
    float* red = (float*)(smraw + (size_t)IQ * NSLOT * 4);     // RW*160 f
    float* sfin = red + RW * JD;                               // 160 (DSMEM)
    float* stot = sfin + JD;                                   // 160
    float* Vsm = stot + JD;                                    // 160
    __half2* Vh2 = (__half2*)(Vsm + JD);                       // 80 half2
    float* scl = (float*)(Vh2 + NSLOT);                        // 16
    __half* eh = (__half*)(scl + 16);                          // IQ*10 half
    float* wsm = (float*)(eh + IQ * NC);                       // IQ floats

    const int tid = threadIdx.x;
    const int warp = tid >> 5;
    const int lane = tid & 31;
    const int b = blockIdx.x >> 2;
    const unsigned int rank = blockIdx.x & 3;
    const bool act = (lane < 20);
    const int sl = act ? 4 * lane : 0;
    float2* red2 = (float2*)red;

    const __half2* gsrc = g_uhat + ((size_t)b * INC + rank * IQ) * NSLOT;

    // ---- stream u_hat quarter -> smem, accumulate pass-0 (c = 0.1) ----
    u64 a0 = 0ull, a1 = 0ull, a2 = 0ull, a3 = 0ull;
    if (act) {
#pragma unroll 2
        for (int i = warp; i < IQ; i += RW) {
            uint4 u = *(const uint4*)(gsrc + (size_t)i * NSLOT + sl);
            *(uint4*)(Usm + (size_t)i * NSLOT + sl) = u;
            add2(a0, h2_to_u64f2(*(__half2*)&u.x));
            add2(a1, h2_to_u64f2(*(__half2*)&u.y));
            add2(a2, h2_to_u64f2(*(__half2*)&u.z));
            add2(a3, h2_to_u64f2(*(__half2*)&u.w));
        }
        F2U t0, t1, t2, t3;
        t0.u = a0; t1.u = a1; t2.u = a2; t3.u = a3;
        red2[warp * 80 + sl + 0] = t0.f;
        red2[warp * 80 + sl + 1] = t1.f;
        red2[warp * 80 + sl + 2] = t2.f;
        red2[warp * 80 + sl + 3] = t3.f;
    }
    __syncthreads();
    if (tid < JD) {
        float s = 0.f;
#pragma unroll
        for (int w = 0; w < RW; w++) s += red[w * JD + tid];
        sfin[tid] = s;
    }
    __syncthreads();
    cluster_sync();
    if (tid < JD) {
        float s = sfin[tid];
#pragma unroll
        for (unsigned int r = 1; r < CSZ; r++)
            s += peer_f32(sfin + tid, rank ^ r);
        stot[tid] = 0.1f * s;
    }
    __syncthreads();
    if (tid < NC) {
        float sq = 0.f;
#pragma unroll
        for (int d = 0; d < DC; d++) {
            float v = stot[tid * DC + d];
            sq = fmaf(v, v, sq);
        }
        scl[tid] = sq / ((1.0f + sq) * sqrtf(sq + EPSQ));
    }
    __syncthreads();
    if (tid < NSLOT) {  // V in f32 (Vsm) and as half2 pairs (Vh2) for the dot
        float sc = scl[tid >> 3];
        float va = sc * stot[2 * tid];
        float vb = sc * stot[2 * tid + 1];
        Vsm[2 * tid] = va;
        Vsm[2 * tid + 1] = vb;
        Vh2[tid] = __floats2half2_rn(va, vb);
    }
    __syncthreads();
    cluster_sync();  // peers done reading sfin; Vsm/Vh2 ready

    // lane mapping for stage A: lane = io*10 + j, io in 0..2, j in 0..9
    const int ioA = lane / 10;
    const int jA = lane - 10 * ioA;
    const bool actA = (lane < 30);

    // ---- passes 1,2 from smem ----
    for (int p = 1; p <= 2; p++) {
        // ===== Stage A: t[i,j] via full local fp16 dot; store e = exp(t) ====
        {
            uint4 vr0 = make_uint4(0, 0, 0, 0), vr1 = vr0;
            if (actA) {
                vr0 = *(const uint4*)(Vh2 + 8 * jA);
                vr1 = *(const uint4*)(Vh2 + 8 * jA + 4);
            }
            __half2 w0 = *(__half2*)&vr0.x, w1 = *(__half2*)&vr0.y;
            __half2 w2 = *(__half2*)&vr0.z, w3 = *(__half2*)&vr0.w;
            __half2 w4 = *(__half2*)&vr1.x, w5 = *(__half2*)&vr1.y;
            __half2 w6 = *(__half2*)&vr1.z, w7 = *(__half2*)&vr1.w;
#pragma unroll 2
            for (int g = warp; g < IQ / 3; g += RW) {
                const int i = g * 3 + ioA;
                if (actA) {
                    const __half2* up = Usm + (size_t)i * NSLOT + 8 * jA;
                    uint4 u0 = *(const uint4*)up;
                    uint4 u1 = *(const uint4*)(up + 4);
                    __half2 acc = __hmul2(*(__half2*)&u0.x, w0);
                    acc = __hfma2(*(__half2*)&u0.y, w1, acc);
                    acc = __hfma2(*(__half2*)&u0.z, w2, acc);
                    acc = __hfma2(*(__half2*)&u0.w, w3, acc);
                    acc = __hfma2(*(__half2*)&u1.x, w4, acc);
                    acc = __hfma2(*(__half2*)&u1.y, w5, acc);
                    acc = __hfma2(*(__half2*)&u1.z, w6, acc);
                    acc = __hfma2(*(__half2*)&u1.w, w7, acc);
                    float2 tf = __half22float2(acc);
                    float e = __expf(tf.x + tf.y);  // |t| small: no max-sub
                    eh[i * NC + jA] = __float2half_rn(e);
                }
            }
        }
        __syncthreads();

        // ===== Stage B: w[i] = 1 / sum_j e[i,j] =====
        if (tid < IQ) {
            const __half2* ep = (const __half2*)(eh + tid * NC);
            float s = 0.f;
#pragma unroll
            for (int q = 0; q < 5; q++) {
                float2 f = __half22float2(ep[q]);
                s += f.x + f.y;
            }
            wsm[tid] = __fdividef(1.f, s);
        }
        __syncthreads();

        // ===== Stage C: s += c * u, c = e[i,j]*w[i] (broadcast loads) =====
        const int jC = lane >> 1;
        u64 s0 = 0ull, s1 = 0ull, s2 = 0ull, s3 = 0ull;
#pragma unroll 4
        for (int i = warp; i < IQ; i += RW) {
            uint4 u = *(const uint4*)(Usm + (size_t)i * NSLOT + sl);
            float cf = __half2float(eh[i * NC + jC]) * wsm[i];
            u64 cc = pack2(cf, cf);
            fma2(s0, h2_to_u64f2(*(__half2*)&u.x), cc);
            fma2(s1, h2_to_u64f2(*(__half2*)&u.y), cc);
            fma2(s2, h2_to_u64f2(*(__half2*)&u.z), cc);
            fma2(s3, h2_to_u64f2(*(__half2*)&u.w), cc);
        }
        if (act) {
            F2U t0, t1, t2, t3;
            t0.u = s0; t1.u = s1; t2.u = s2; t3.u = s3;
            red2[warp * 80 + sl + 0] = t0.f;
            red2[warp * 80 + sl + 1] = t1.f;
            red2[warp * 80 + sl + 2] = t2.f;
            red2[warp * 80 + sl + 3] = t3.f;
        }
        __syncthreads();
        if (tid < JD) {
            float s = 0.f;
#pragma unroll
            for (int w = 0; w < RW; w++) s += red[w * JD + tid];
            sfin[tid] = s;
        }
        __syncthreads();
        cluster_sync();
        if (tid < JD) {
            float s = sfin[tid];
#pragma unroll
            for (unsigned int r = 1; r < CSZ; r++)
                s += peer_f32(sfin + tid, rank ^ r);
            stot[tid] = s;
        }
        __syncthreads();
        if (tid < NC) {
            float sq = 0.f;
#pragma unroll
            for (int d = 0; d < DC; d++) {
                float v = stot[tid * DC + d];
                sq = fmaf(v, v, sq);
            }
            scl[tid] = sq / ((1.0f + sq) * sqrtf(sq + EPSQ));
        }
        __syncthreads();
        if (p == 1) {
            if (tid < NSLOT) {  // V += v; refresh Vh2
                float sc = scl[tid >> 3];
                float va = Vsm[2 * tid] + sc * stot[2 * tid];
                float vb = Vsm[2 * tid + 1] + sc * stot[2 * tid + 1];
                Vsm[2 * tid] = va;
                Vsm[2 * tid + 1] = vb;
                Vh2[tid] = __floats2half2_rn(va, vb);
            }
            __syncthreads();
        } else {
            if (rank == 0 && tid < JD)
                out[(size_t)b * JD + tid] = scl[tid >> 4] * stot[tid];
        }
        cluster_sync();  // sfin reuse / exit safety
    }
}

// ---------------------------------------------------------------------------
extern "C" void kernel_launch(void* const* d_in, const int* in_sizes, int n_in,
                              void* d_out, int out_size) {
    const float* inputs = (const float*)d_in[0];  // [512, 1152, 8]
    const float* W = (const float*)d_in[1];       // [10, 1152, 16, 8]
    float* out = (float*)d_out;                   // [512, 10, 16]

    uhat_kernel<<<INC, 256>>>(inputs, W);

    const int smem = IQ * NSLOT * 4 + (RW * JD + 3 * JD) * 4 + NSLOT * 4 +
                     16 * 4 + IQ * NC * 2 + IQ * 4;  // ~107 KB
    cudaFuncSetAttribute(route_kernel,
                         cudaFuncAttributeMaxDynamicSharedMemorySize, smem);
    route_kernel<<<BATCH * CSZ, 384, smem>>>(out);
}

// round 9
// speedup vs baseline: 1.2404x; 1.2048x over previous
#include <cuda_runtime.h>
#include <cuda_fp16.h>
#include <cstdint>

#define BATCH 512
#define INC   1152
#define NC    10
#define DC    16
#define JD    160      // NC*DC
#define NSLOT 80       // half2 slots per (b,i): slot m holds jd {2m, 2m+1}
#define CSZ   4        // cluster CTAs per batch
#define IQ    288      // i-range per route CTA (INC / CSZ)
#define RW    12       // warps per route CTA (384 threads)
#define EPSQ  1e-7f
#define UBYTES (IQ * NSLOT * 4)   // 92160 B per CTA quarter

typedef unsigned long long u64;

// u_hat in fp16, layout [b][i][slot], slot m = jd pair (2m, 2m+1). 188 MB.
__device__ __half2 g_uhat[(size_t)BATCH * INC * NSLOT];

// ---------------------------------------------------------------------------
// helpers
// ---------------------------------------------------------------------------
__device__ __forceinline__ void cluster_sync() {
    asm volatile("barrier.cluster.arrive.aligned;\n\t"
                 "barrier.cluster.wait.aligned;" ::: "memory");
}

__device__ __forceinline__ float peer_f32(const float* p, unsigned int peer) {
    unsigned int a = (unsigned int)__cvta_generic_to_shared(p);
    unsigned int r;
    asm("mapa.shared::cluster.u32 %0, %1, %2;" : "=r"(r) : "r"(a), "r"(peer));
    float v;
    asm volatile("ld.shared::cluster.f32 %0, [%1];" : "=f"(v) : "r"(r));
    return v;
}

__device__ __forceinline__ u64 pack2(float lo, float hi) {
    u64 r;
    asm("mov.b64 %0, {%1, %2};" : "=l"(r) : "f"(lo), "f"(hi));
    return r;
}
__device__ __forceinline__ void fma2(u64& d, u64 a, u64 b) {
    asm("fma.rn.f32x2 %0, %1, %2, %3;" : "=l"(d) : "l"(a), "l"(b), "l"(d));
}
__device__ __forceinline__ void add2(u64& d, u64 a) {
    asm("add.rn.f32x2 %0, %0, %1;" : "+l"(d) : "l"(a));
}
// f32x2 {lo,hi} -> half2 {.x=lo, .y=hi}
__device__ __forceinline__ __half2 f2_to_h2(u64 v) {
    float lo, hi;
    asm("mov.b64 {%0, %1}, %2;" : "=f"(lo), "=f"(hi) : "l"(v));
    unsigned int r;
    asm("cvt.rn.f16x2.f32 %0, %1, %2;" : "=r"(r) : "f"(hi), "f"(lo));
    return *(__half2*)&r;
}
union F2U { float2 f; u64 u; };

__device__ __forceinline__ u64 h2_to_u64f2(__half2 h) {
    F2U t;
    t.f = __half22float2(h);
    return t.u;
}

// ---------------------------------------------------------------------------
// Kernel A: u_hat[b,i,jd] = sum_k inputs[b,i,k] * W[jd(i),k], fp16 output.
// R6 configuration: FFMA2 + 1-deep input prefetch, unroll 2.
// ---------------------------------------------------------------------------
__global__ __launch_bounds__(256) void uhat_kernel(const float* __restrict__ inp,
                                                   const float* __restrict__ W) {
    const int warp = threadIdx.x >> 5;
    const int lane = threadIdx.x & 31;
    const int gw = blockIdx.x * 8 + warp;   // [0, 9216)
    const int i = gw >> 3;
    const int chunk = gw & 7;

    // wp?[k] = pack(W[jd0][k], W[jd0+1][k])
    u64 wpA[8], wpB[8], wpC[8];
#define LOADW(dst, jd0)                                                        \
    {                                                                          \
        const int j_ = (jd0) >> 4, d_ = (jd0) & 15;                            \
        const float4* p_ =                                                     \
            (const float4*)(W + (((size_t)j_ * INC + i) * DC + d_) * 8);       \
        float4 q0 = __ldg(p_), q1 = __ldg(p_ + 1), q2 = __ldg(p_ + 2),         \
               q3 = __ldg(p_ + 3);                                             \
        dst[0] = pack2(q0.x, q2.x); dst[1] = pack2(q0.y, q2.y);                \
        dst[2] = pack2(q0.z, q2.z); dst[3] = pack2(q0.w, q2.w);                \
        dst[4] = pack2(q1.x, q3.x); dst[5] = pack2(q1.y, q3.y);                \
        dst[6] = pack2(q1.z, q3.z); dst[7] = pack2(q1.w, q3.w);                \
    }
    LOADW(wpA, 2 * lane);
    LOADW(wpB, 64 + 2 * lane);
    if (lane < 16) {
        LOADW(wpC, 128 + 2 * lane);
    } else {
#pragma unroll
        for (int k = 0; k < 8; k++) wpC[k] = 0ull;
    }
#undef LOADW

    const int b0 = chunk * 64;
    const float4* ip0 = (const float4*)(inp + ((size_t)b0 * INC + i) * 8);
    float4 x = __ldg(ip0), y = __ldg(ip0 + 1);
#pragma unroll 2
    for (int bb = 0; bb < 64; bb++) {
        u64 in2[8];
        in2[0] = pack2(x.x, x.x); in2[1] = pack2(x.y, x.y);
        in2[2] = pack2(x.z, x.z); in2[3] = pack2(x.w, x.w);
        in2[4] = pack2(y.x, y.x); in2[5] = pack2(y.y, y.y);
        in2[6] = pack2(y.z, y.z); in2[7] = pack2(y.w, y.w);
        if (bb + 1 < 64) {  // prefetch next batch's inputs
            const float4* ipn =
                (const float4*)(inp + ((size_t)(b0 + bb + 1) * INC + i) * 8);
            x = __ldg(ipn);
            y = __ldg(ipn + 1);
        }

        u64 aA = 0ull, aB = 0ull, aC = 0ull;
#pragma unroll
        for (int k = 0; k < 8; k++) {
            fma2(aA, in2[k], wpA[k]);
            fma2(aB, in2[k], wpB[k]);
            fma2(aC, in2[k], wpC[k]);
        }
        __half2* up = g_uhat + ((size_t)(b0 + bb) * INC + i) * NSLOT;
        up[lane] = f2_to_h2(aA);
        up[32 + lane] = f2_to_h2(aB);
        if (lane < 16) up[64 + lane] = f2_to_h2(aC);
    }
}

// ---------------------------------------------------------------------------
// Kernel R: routing. Cluster of 4 CTAs per batch. The u_hat quarter now
// arrives via ONE cp.async.bulk (TMA) into smem -- no per-warp LDG stalls,
// no L1tex queue pileup. Pass-0 sum reads smem. Then stages per pass:
//   A: lane=(i_off,j) computes full fp16 dot t[i,j], stores e=exp(t) (fp16)
//   B: thread-per-i stores w[i] = 1/sum_j e[i,j]
//   C: lane l<20 accumulates s += (e[i,j]*w[i]) * u[i,slot], broadcast loads.
// ---------------------------------------------------------------------------
__global__ __launch_bounds__(384, 2) __cluster_dims__(CSZ, 1, 1)
void route_kernel(float* __restrict__ out) {
    extern __shared__ char smraw[];
    __half2* Usm = (__half2*)smraw;                            // 92160 B
    float* red = (float*)(smraw + UBYTES);                     // RW*160 f
    float* sfin = red + RW * JD;                               // 160 (DSMEM)
    float* stot = sfin + JD;                                   // 160
    float* Vsm = stot + JD;                                    // 160
    __half2* Vh2 = (__half2*)(Vsm + JD);                       // 80 half2
    float* scl = (float*)(Vh2 + NSLOT);                        // 16
    __half* eh = (__half*)(scl + 16);                          // IQ*10 half
    float* wsm = (float*)(eh + IQ * NC);                       // IQ floats
    u64* mbar = (u64*)(wsm + IQ);                              // 8 B mbarrier

    const int tid = threadIdx.x;
    const int warp = tid >> 5;
    const int lane = tid & 31;
    const int b = blockIdx.x >> 2;
    const unsigned int rank = blockIdx.x & 3;
    const bool act = (lane < 20);
    const int sl = act ? 4 * lane : 0;
    float2* red2 = (float2*)red;
    const unsigned int mbar_a = (unsigned int)__cvta_generic_to_shared(mbar);
    const unsigned int usm_a = (unsigned int)__cvta_generic_to_shared(Usm);

    // ---- single bulk async copy: g_uhat quarter -> smem ----
    if (tid == 0) {
        asm volatile("mbarrier.init.shared.b64 [%0], %1;" ::"r"(mbar_a),
                     "r"(1u)
                     : "memory");
    }
    __syncthreads();
    if (tid == 0) {
        const __half2* gsrc =
            g_uhat + ((size_t)b * INC + rank * IQ) * NSLOT;
        asm volatile(
            "mbarrier.arrive.expect_tx.shared.b64 _, [%0], %1;" ::"r"(mbar_a),
            "r"((unsigned int)UBYTES)
            : "memory");
        asm volatile(
            "cp.async.bulk.shared::cta.global.mbarrier::complete_tx::bytes "
            "[%0], [%1], %2, [%3];" ::"r"(usm_a),
            "l"((const void*)gsrc), "r"((unsigned int)UBYTES), "r"(mbar_a)
            : "memory");
    }
    {  // all threads wait for TMA completion (parity 0)
        unsigned int done;
        asm volatile(
            "{\n\t.reg .pred p;\n\t"
            "mbarrier.try_wait.parity.acquire.cta.shared::cta.b64 p, [%1], %2;\n\t"
            "selp.b32 %0, 1, 0, p;\n\t}"
            : "=r"(done)
            : "r"(mbar_a), "r"(0u)
            : "memory");
        while (!done) {
            asm volatile(
                "{\n\t.reg .pred p;\n\t"
                "mbarrier.try_wait.parity.acquire.cta.shared::cta.b64 p, [%1], %2, 0x989680;\n\t"
                "selp.b32 %0, 1, 0, p;\n\t}"
                : "=r"(done)
                : "r"(mbar_a), "r"(0u)
                : "memory");
        }
    }

    // ---- pass-0 (c = 0.1 uniform): sum u over i, from smem ----
    u64 a0 = 0ull, a1 = 0ull, a2 = 0ull, a3 = 0ull;
    if (act) {
#pragma unroll 4
        for (int i = warp; i < IQ; i += RW) {
            uint4 u = *(const uint4*)(Usm + (size_t)i * NSLOT + sl);
            add2(a0, h2_to_u64f2(*(__half2*)&u.x));
            add2(a1, h2_to_u64f2(*(__half2*)&u.y));
            add2(a2, h2_to_u64f2(*(__half2*)&u.z));
            add2(a3, h2_to_u64f2(*(__half2*)&u.w));
        }
        F2U t0, t1, t2, t3;
        t0.u = a0; t1.u = a1; t2.u = a2; t3.u = a3;
        red2[warp * 80 + sl + 0] = t0.f;
        red2[warp * 80 + sl + 1] = t1.f;
        red2[warp * 80 + sl + 2] = t2.f;
        red2[warp * 80 + sl + 3] = t3.f;
    }
    __syncthreads();
    if (tid < JD) {
        float s = 0.f;
#pragma unroll
        for (int w = 0; w < RW; w++) s += red[w * JD + tid];
        sfin[tid] = s;
    }
    __syncthreads();
    cluster_sync();
    if (tid < JD) {
        float s = sfin[tid];
#pragma unroll
        for (unsigned int r = 1; r < CSZ; r++)
            s += peer_f32(sfin + tid, rank ^ r);
        stot[tid] = 0.1f * s;
    }
    __syncthreads();
    if (tid < NC) {
        float sq = 0.f;
#pragma unroll
        for (int d = 0; d < DC; d++) {
            float v = stot[tid * DC + d];
            sq = fmaf(v, v, sq);
        }
        scl[tid] = sq / ((1.0f + sq) * sqrtf(sq + EPSQ));
    }
    __syncthreads();
    if (tid < NSLOT) {  // V in f32 (Vsm) and as half2 pairs (Vh2) for the dot
        float sc = scl[tid >> 3];
        float va = sc * stot[2 * tid];
        float vb = sc * stot[2 * tid + 1];
        Vsm[2 * tid] = va;
        Vsm[2 * tid + 1] = vb;
        Vh2[tid] = __floats2half2_rn(va, vb);
    }
    __syncthreads();
    cluster_sync();  // peers done reading sfin; Vsm/Vh2 ready

    // lane mapping for stage A: lane = io*10 + j, io in 0..2, j in 0..9
    const int ioA = lane / 10;
    const int jA = lane - 10 * ioA;
    const bool actA = (lane < 30);

    // ---- passes 1,2 from smem ----
    for (int p = 1; p <= 2; p++) {
        // ===== Stage A: t[i,j] via full local fp16 dot; store e = exp(t) ====
        {
            uint4 vr0 = make_uint4(0, 0, 0, 0), vr1 = vr0;
            if (actA) {
                vr0 = *(const uint4*)(Vh2 + 8 * jA);
                vr1 = *(const uint4*)(Vh2 + 8 * jA + 4);
            }
            __half2 w0 = *(__half2*)&vr0.x, w1 = *(__half2*)&vr0.y;
            __half2 w2 = *(__half2*)&vr0.z, w3 = *(__half2*)&vr0.w;
            __half2 w4 = *(__half2*)&vr1.x, w5 = *(__half2*)&vr1.y;
            __half2 w6 = *(__half2*)&vr1.z, w7 = *(__half2*)&vr1.w;
#pragma unroll 4
            for (int g = warp; g < IQ / 3; g += RW) {
                const int i = g * 3 + ioA;
                if (actA) {
                    const __half2* up = Usm + (size_t)i * NSLOT + 8 * jA;
                    uint4 u0 = *(const uint4*)up;
                    uint4 u1 = *(const uint4*)(up + 4);
                    __half2 acc = __hmul2(*(__half2*)&u0.x, w0);
                    acc = __hfma2(*(__half2*)&u0.y, w1, acc);
                    acc = __hfma2(*(__half2*)&u0.z, w2, acc);
                    acc = __hfma2(*(__half2*)&u0.w, w3, acc);
                    acc = __hfma2(*(__half2*)&u1.x, w4, acc);
                    acc = __hfma2(*(__half2*)&u1.y, w5, acc);
                    acc = __hfma2(*(__half2*)&u1.z, w6, acc);
                    acc = __hfma2(*(__half2*)&u1.w, w7, acc);
                    float2 tf = __half22float2(acc);
                    float e = __expf(tf.x + tf.y);  // |t| small: no max-sub
                    eh[i * NC + jA] = __float2half_rn(e);
                }
            }
        }
        __syncthreads();

        // ===== Stage B: w[i] = 1 / sum_j e[i,j] =====
        if (tid < IQ) {
            const __half2* ep = (const __half2*)(eh + tid * NC);
            float s = 0.f;
#pragma unroll
            for (int q = 0; q < 5; q++) {
                float2 f = __half22float2(ep[q]);
                s += f.x + f.y;
            }
            wsm[tid] = __fdividef(1.f, s);
        }
        __syncthreads();

        // ===== Stage C: s += c * u, c = e[i,j]*w[i] (broadcast loads) =====
        const int jC = lane >> 1;
        u64 s0 = 0ull, s1 = 0ull, s2 = 0ull, s3 = 0ull;
#pragma unroll 4
        for (int i = warp; i < IQ; i += RW) {
            uint4 u = *(const uint4*)(Usm + (size_t)i * NSLOT + sl);
            float cf = __half2float(eh[i * NC + jC]) * wsm[i];
            u64 cc = pack2(cf, cf);
            fma2(s0, h2_to_u64f2(*(__half2*)&u.x), cc);
            fma2(s1, h2_to_u64f2(*(__half2*)&u.y), cc);
            fma2(s2, h2_to_u64f2(*(__half2*)&u.z), cc);
            fma2(s3, h2_to_u64f2(*(__half2*)&u.w), cc);
        }
        if (act) {
            F2U t0, t1, t2, t3;
            t0.u = s0; t1.u = s1; t2.u = s2; t3.u = s3;
            red2[warp * 80 + sl + 0] = t0.f;
            red2[warp * 80 + sl + 1] = t1.f;
            red2[warp * 80 + sl + 2] = t2.f;
            red2[warp * 80 + sl + 3] = t3.f;
        }
        __syncthreads();
        if (tid < JD) {
            float s = 0.f;
#pragma unroll
            for (int w = 0; w < RW; w++) s += red[w * JD + tid];
            sfin[tid] = s;
        }
        __syncthreads();
        cluster_sync();
        if (tid < JD) {
            float s = sfin[tid];
#pragma unroll
            for (unsigned int r = 1; r < CSZ; r++)
                s += peer_f32(sfin + tid, rank ^ r);
            stot[tid] = s;
        }
        __syncthreads();
        if (tid < NC) {
            float sq = 0.f;
#pragma unroll
            for (int d = 0; d < DC; d++) {
                float v = stot[tid * DC + d];
                sq = fmaf(v, v, sq);
            }
            scl[tid] = sq / ((1.0f + sq) * sqrtf(sq + EPSQ));
        }
        __syncthreads();
        if (p == 1) {
            if (tid < NSLOT) {  // V += v; refresh Vh2
                float sc = scl[tid >> 3];
                float va = Vsm[2 * tid] + sc * stot[2 * tid];
                float vb = Vsm[2 * tid + 1] + sc * stot[2 * tid + 1];
                Vsm[2 * tid] = va;
                Vsm[2 * tid + 1] = vb;
                Vh2[tid] = __floats2half2_rn(va, vb);
            }
            __syncthreads();
        } else {
            if (rank == 0 && tid < JD)
                out[(size_t)b * JD + tid] = scl[tid >> 4] * stot[tid];
        }
        cluster_sync();  // sfin reuse / exit safety
    }
}

// ---------------------------------------------------------------------------
extern "C" void kernel_launch(void* const* d_in, const int* in_sizes, int n_in,
                              void* d_out, int out_size) {
    const float* inputs = (const float*)d_in[0];  // [512, 1152, 8]
    const float* W = (const float*)d_in[1];       // [10, 1152, 16, 8]
    float* out = (float*)d_out;                   // [512, 10, 16]

    uhat_kernel<<<INC, 256>>>(inputs, W);

    const int smem = UBYTES + (RW * JD + 3 * JD) * 4 + NSLOT * 4 + 16 * 4 +
                     IQ * NC * 2 + IQ * 4 + 16;  // ~107 KB (+mbar)
    cudaFuncSetAttribute(route_kernel,
                         cudaFuncAttributeMaxDynamicSharedMemorySize, smem);
    route_kernel<<<BATCH * CSZ, 384, smem>>>(out);
}

// round 10
// speedup vs baseline: 1.4715x; 1.1863x over previous
#include <cuda_runtime.h>
#include <cuda_fp16.h>
#include <cstdint>

#define BATCH 512
#define INC   1152
#define NC    10
#define DC    16
#define JD    160      // NC*DC
#define NSLOT 80       // half2 slots per (b,i): slot m holds jd {2m, 2m+1}
#define CSZ   4        // cluster CTAs per batch
#define IQ    288      // i-range per route CTA (INC / CSZ)
#define RW    12       // warps per route CTA (384 threads)
#define EPSQ  1e-7f
#define UBYTES (IQ * NSLOT * 4)   // 92160 B per CTA quarter

typedef unsigned long long u64;

// u_hat in fp16, layout [b][i][slot], slot m = jd pair (2m, 2m+1). 188 MB.
__device__ __half2 g_uhat[(size_t)BATCH * INC * NSLOT];

// ---------------------------------------------------------------------------
// helpers
// ---------------------------------------------------------------------------
__device__ __forceinline__ void cluster_sync() {
    asm volatile("barrier.cluster.arrive.aligned;\n\t"
                 "barrier.cluster.wait.aligned;" ::: "memory");
}

__device__ __forceinline__ float peer_f32(const float* p, unsigned int peer) {
    unsigned int a = (unsigned int)__cvta_generic_to_shared(p);
    unsigned int r;
    asm("mapa.shared::cluster.u32 %0, %1, %2;" : "=r"(r) : "r"(a), "r"(peer));
    float v;
    asm volatile("ld.shared::cluster.f32 %0, [%1];" : "=f"(v) : "r"(r));
    return v;
}

__device__ __forceinline__ u64 pack2(float lo, float hi) {
    u64 r;
    asm("mov.b64 %0, {%1, %2};" : "=l"(r) : "f"(lo), "f"(hi));
    return r;
}
__device__ __forceinline__ void fma2(u64& d, u64 a, u64 b) {
    asm("fma.rn.f32x2 %0, %1, %2, %3;" : "=l"(d) : "l"(a), "l"(b), "l"(d));
}
__device__ __forceinline__ void add2(u64& d, u64 a) {
    asm("add.rn.f32x2 %0, %0, %1;" : "+l"(d) : "l"(a));
}
// f32x2 {lo,hi} -> half2 {.x=lo, .y=hi}
__device__ __forceinline__ __half2 f2_to_h2(u64 v) {
    float lo, hi;
    asm("mov.b64 {%0, %1}, %2;" : "=f"(lo), "=f"(hi) : "l"(v));
    unsigned int r;
    asm("cvt.rn.f16x2.f32 %0, %1, %2;" : "=r"(r) : "f"(hi), "f"(lo));
    return *(__half2*)&r;
}
union F2U { float2 f; u64 u; };

__device__ __forceinline__ u64 h2_to_u64f2(__half2 h) {
    F2U t;
    t.f = __half22float2(h);
    return t.u;
}

// ---------------------------------------------------------------------------
// Kernel A: u_hat[b,i,jd] = sum_k inputs[b,i,k] * W[jd(i),k], fp16 output.
// One CTA per i. All 512 batches' inputs for this i (16 KB) are staged into
// smem up-front (batched MLP-4 LDGs) -- the main loop then has ZERO global
// loads: broadcast LDS.128 + FFMA2 + STG only.
// ---------------------------------------------------------------------------
__global__ __launch_bounds__(256) void uhat_kernel(const float* __restrict__ inp,
                                                   const float* __restrict__ W) {
    __shared__ float4 sin[BATCH][2];   // 16 KB: inputs[b][i][0..7]

    const int tid = threadIdx.x;
    const int warp = tid >> 5;
    const int lane = tid & 31;
    const int i = blockIdx.x;

    // ---- stage inputs: thread t loads b = t, t+256 (2x2 LDG.128, MLP 4) ----
    {
        const float4* p0 = (const float4*)(inp + ((size_t)tid * INC + i) * 8);
        const float4* p1 =
            (const float4*)(inp + ((size_t)(tid + 256) * INC + i) * 8);
        float4 a0 = __ldg(p0), a1 = __ldg(p0 + 1);
        float4 b0 = __ldg(p1), b1 = __ldg(p1 + 1);
        sin[tid][0] = a0;
        sin[tid][1] = a1;
        sin[tid + 256][0] = b0;
        sin[tid + 256][1] = b1;
    }

    // ---- W pairs packed as f32x2 in registers ----
    u64 wpA[8], wpB[8], wpC[8];
#define LOADW(dst, jd0)                                                        \
    {                                                                          \
        const int j_ = (jd0) >> 4, d_ = (jd0) & 15;                            \
        const float4* p_ =                                                     \
            (const float4*)(W + (((size_t)j_ * INC + i) * DC + d_) * 8);       \
        float4 q0 = __ldg(p_), q1 = __ldg(p_ + 1), q2 = __ldg(p_ + 2),         \
               q3 = __ldg(p_ + 3);                                             \
        dst[0] = pack2(q0.x, q2.x); dst[1] = pack2(q0.y, q2.y);                \
        dst[2] = pack2(q0.z, q2.z); dst[3] = pack2(q0.w, q2.w);                \
        dst[4] = pack2(q1.x, q3.x); dst[5] = pack2(q1.y, q3.y);                \
        dst[6] = pack2(q1.z, q3.z); dst[7] = pack2(q1.w, q3.w);                \
    }
    LOADW(wpA, 2 * lane);
    LOADW(wpB, 64 + 2 * lane);
    if (lane < 16) {
        LOADW(wpC, 128 + 2 * lane);
    } else {
#pragma unroll
        for (int k = 0; k < 8; k++) wpC[k] = 0ull;
    }
#undef LOADW

    __syncthreads();

    // ---- main loop: warp owns 64 batches; inputs via broadcast LDS ----
    const int b0 = warp * 64;
#pragma unroll 2
    for (int bb = 0; bb < 64; bb++) {
        const int b = b0 + bb;
        float4 x = sin[b][0], y = sin[b][1];

        u64 in2[8];
        in2[0] = pack2(x.x, x.x); in2[1] = pack2(x.y, x.y);
        in2[2] = pack2(x.z, x.z); in2[3] = pack2(x.w, x.w);
        in2[4] = pack2(y.x, y.x); in2[5] = pack2(y.y, y.y);
        in2[6] = pack2(y.z, y.z); in2[7] = pack2(y.w, y.w);

        u64 aA = 0ull, aB = 0ull, aC = 0ull;
#pragma unroll
        for (int k = 0; k < 8; k++) {
            fma2(aA, in2[k], wpA[k]);
            fma2(aB, in2[k], wpB[k]);
            fma2(aC, in2[k], wpC[k]);
        }
        __half2* up = g_uhat + ((size_t)b * INC + i) * NSLOT;
        up[lane] = f2_to_h2(aA);
        up[32 + lane] = f2_to_h2(aB);
        if (lane < 16) up[64 + lane] = f2_to_h2(aC);
    }
}

// ---------------------------------------------------------------------------
// Kernel R: routing (unchanged from R9 winner). Cluster of 4 CTAs per batch.
// u_hat quarter arrives via ONE cp.async.bulk (TMA) into smem. Stages:
//   A: lane=(i_off,j) computes full fp16 dot t[i,j], stores e=exp(t) (fp16)
//   B: thread-per-i stores w[i] = 1/sum_j e[i,j]
//   C: lane l<20 accumulates s += (e[i,j]*w[i]) * u[i,slot], broadcast loads.
// ---------------------------------------------------------------------------
__global__ __launch_bounds__(384, 2) __cluster_dims__(CSZ, 1, 1)
void route_kernel(float* __restrict__ out) {
    extern __shared__ char smraw[];
    __half2* Usm = (__half2*)smraw;                            // 92160 B
    float* red = (float*)(smraw + UBYTES);                     // RW*160 f
    float* sfin = red + RW * JD;                               // 160 (DSMEM)
    float* stot = sfin + JD;                                   // 160
    float* Vsm = stot + JD;                                    // 160
    __half2* Vh2 = (__half2*)(Vsm + JD);                       // 80 half2
    float* scl = (float*)(Vh2 + NSLOT);                        // 16
    __half* eh = (__half*)(scl + 16);                          // IQ*10 half
    float* wsm = (float*)(eh + IQ * NC);                       // IQ floats
    u64* mbar = (u64*)(wsm + IQ);                              // 8 B mbarrier

    const int tid = threadIdx.x;
    const int warp = tid >> 5;
    const int lane = tid & 31;
    const int b = blockIdx.x >> 2;
    const unsigned int rank = blockIdx.x & 3;
    const bool act = (lane < 20);
    const int sl = act ? 4 * lane : 0;
    float2* red2 = (float2*)red;
    const unsigned int mbar_a = (unsigned int)__cvta_generic_to_shared(mbar);
    const unsigned int usm_a = (unsigned int)__cvta_generic_to_shared(Usm);

    // ---- single bulk async copy: g_uhat quarter -> smem ----
    if (tid == 0) {
        asm volatile("mbarrier.init.shared.b64 [%0], %1;" ::"r"(mbar_a),
                     "r"(1u)
                     : "memory");
    }
    __syncthreads();
    if (tid == 0) {
        const __half2* gsrc =
            g_uhat + ((size_t)b * INC + rank * IQ) * NSLOT;
        asm volatile(
            "mbarrier.arrive.expect_tx.shared.b64 _, [%0], %1;" ::"r"(mbar_a),
            "r"((unsigned int)UBYTES)
            : "memory");
        asm volatile(
            "cp.async.bulk.shared::cta.global.mbarrier::complete_tx::bytes "
            "[%0], [%1], %2, [%3];" ::"r"(usm_a),
            "l"((const void*)gsrc), "r"((unsigned int)UBYTES), "r"(mbar_a)
            : "memory");
    }
    {  // all threads wait for TMA completion (parity 0)
        unsigned int done;
        asm volatile(
            "{\n\t.reg .pred p;\n\t"
            "mbarrier.try_wait.parity.acquire.cta.shared::cta.b64 p, [%1], %2;\n\t"
            "selp.b32 %0, 1, 0, p;\n\t}"
            : "=r"(done)
            : "r"(mbar_a), "r"(0u)
            : "memory");
        while (!done) {
            asm volatile(
                "{\n\t.reg .pred p;\n\t"
                "mbarrier.try_wait.parity.acquire.cta.shared::cta.b64 p, [%1], %2, 0x989680;\n\t"
                "selp.b32 %0, 1, 0, p;\n\t}"
                : "=r"(done)
                : "r"(mbar_a), "r"(0u)
                : "memory");
        }
    }

    // ---- pass-0 (c = 0.1 uniform): sum u over i, from smem ----
    u64 a0 = 0ull, a1 = 0ull, a2 = 0ull, a3 = 0ull;
    if (act) {
#pragma unroll 4
        for (int i = warp; i < IQ; i += RW) {
            uint4 u = *(const uint4*)(Usm + (size_t)i * NSLOT + sl);
            add2(a0, h2_to_u64f2(*(__half2*)&u.x));
            add2(a1, h2_to_u64f2(*(__half2*)&u.y));
            add2(a2, h2_to_u64f2(*(__half2*)&u.z));
            add2(a3, h2_to_u64f2(*(__half2*)&u.w));
        }
        F2U t0, t1, t2, t3;
        t0.u = a0; t1.u = a1; t2.u = a2; t3.u = a3;
        red2[warp * 80 + sl + 0] = t0.f;
        red2[warp * 80 + sl + 1] = t1.f;
        red2[warp * 80 + sl + 2] = t2.f;
        red2[warp * 80 + sl + 3] = t3.f;
    }
    __syncthreads();
    if (tid < JD) {
        float s = 0.f;
#pragma unroll
        for (int w = 0; w < RW; w++) s += red[w * JD + tid];
        sfin[tid] = s;
    }
    __syncthreads();
    cluster_sync();
    if (tid < JD) {
        float s = sfin[tid];
#pragma unroll
        for (unsigned int r = 1; r < CSZ; r++)
            s += peer_f32(sfin + tid, rank ^ r);
        stot[tid] = 0.1f * s;
    }
    __syncthreads();
    if (tid < NC) {
        float sq = 0.f;
#pragma unroll
        for (int d = 0; d < DC; d++) {
            float v = stot[tid * DC + d];
            sq = fmaf(v, v, sq);
        }
        scl[tid] = sq / ((1.0f + sq) * sqrtf(sq + EPSQ));
    }
    __syncthreads();
    if (tid < NSLOT) {  // V in f32 (Vsm) and as half2 pairs (Vh2) for the dot
        float sc = scl[tid >> 3];
        float va = sc * stot[2 * tid];
        float vb = sc * stot[2 * tid + 1];
        Vsm[2 * tid] = va;
        Vsm[2 * tid + 1] = vb;
        Vh2[tid] = __floats2half2_rn(va, vb);
    }
    __syncthreads();
    cluster_sync();  // peers done reading sfin; Vsm/Vh2 ready

    // lane mapping for stage A: lane = io*10 + j, io in 0..2, j in 0..9
    const int ioA = lane / 10;
    const int jA = lane - 10 * ioA;
    const bool actA = (lane < 30);

    // ---- passes 1,2 from smem ----
    for (int p = 1; p <= 2; p++) {
        // ===== Stage A: t[i,j] via full local fp16 dot; store e = exp(t) ====
        {
            uint4 vr0 = make_uint4(0, 0, 0, 0), vr1 = vr0;
            if (actA) {
                vr0 = *(const uint4*)(Vh2 + 8 * jA);
                vr1 = *(const uint4*)(Vh2 + 8 * jA + 4);
            }
            __half2 w0 = *(__half2*)&vr0.x, w1 = *(__half2*)&vr0.y;
            __half2 w2 = *(__half2*)&vr0.z, w3 = *(__half2*)&vr0.w;
            __half2 w4 = *(__half2*)&vr1.x, w5 = *(__half2*)&vr1.y;
            __half2 w6 = *(__half2*)&vr1.z, w7 = *(__half2*)&vr1.w;
#pragma unroll 4
            for (int g = warp; g < IQ / 3; g += RW) {
                const int i = g * 3 + ioA;
                if (actA) {
                    const __half2* up = Usm + (size_t)i * NSLOT + 8 * jA;
                    uint4 u0 = *(const uint4*)up;
                    uint4 u1 = *(const uint4*)(up + 4);
                    __half2 acc = __hmul2(*(__half2*)&u0.x, w0);
                    acc = __hfma2(*(__half2*)&u0.y, w1, acc);
                    acc = __hfma2(*(__half2*)&u0.z, w2, acc);
                    acc = __hfma2(*(__half2*)&u0.w, w3, acc);
                    acc = __hfma2(*(__half2*)&u1.x, w4, acc);
                    acc = __hfma2(*(__half2*)&u1.y, w5, acc);
                    acc = __hfma2(*(__half2*)&u1.z, w6, acc);
                    acc = __hfma2(*(__half2*)&u1.w, w7, acc);
                    float2 tf = __half22float2(acc);
                    float e = __expf(tf.x + tf.y);  // |t| small: no max-sub
                    eh[i * NC + jA] = __float2half_rn(e);
                }
            }
        }
        __syncthreads();

        // ===== Stage B: w[i] = 1 / sum_j e[i,j] =====
        if (tid < IQ) {
            const __half2* ep = (const __half2*)(eh + tid * NC);
            float s = 0.f;
#pragma unroll
            for (int q = 0; q < 5; q++) {
                float2 f = __half22float2(ep[q]);
                s += f.x + f.y;
            }
            wsm[tid] = __fdividef(1.f, s);
        }
        __syncthreads();

        // ===== Stage C: s += c * u, c = e[i,j]*w[i] (broadcast loads) =====
        const int jC = lane >> 1;
        u64 s0 = 0ull, s1 = 0ull, s2 = 0ull, s3 = 0ull;
#pragma unroll 4
        for (int i = warp; i < IQ; i += RW) {
            uint4 u = *(const uint4*)(Usm + (size_t)i * NSLOT + sl);
            float cf = __half2float(eh[i * NC + jC]) * wsm[i];
            u64 cc = pack2(cf, cf);
            fma2(s0, h2_to_u64f2(*(__half2*)&u.x), cc);
            fma2(s1, h2_to_u64f2(*(__half2*)&u.y), cc);
            fma2(s2, h2_to_u64f2(*(__half2*)&u.z), cc);
            fma2(s3, h2_to_u64f2(*(__half2*)&u.w), cc);
        }
        if (act) {
            F2U t0, t1, t2, t3;
            t0.u = s0; t1.u = s1; t2.u = s2; t3.u = s3;
            red2[warp * 80 + sl + 0] = t0.f;
            red2[warp * 80 + sl + 1] = t1.f;
            red2[warp * 80 + sl + 2] = t2.f;
            red2[warp * 80 + sl + 3] = t3.f;
        }
        __syncthreads();
        if (tid < JD) {
            float s = 0.f;
#pragma unroll
            for (int w = 0; w < RW; w++) s += red[w * JD + tid];
            sfin[tid] = s;
        }
        __syncthreads();
        cluster_sync();
        if (tid < JD) {
            float s = sfin[tid];
#pragma unroll
            for (unsigned int r = 1; r < CSZ; r++)
                s += peer_f32(sfin + tid, rank ^ r);
            stot[tid] = s;
        }
        __syncthreads();
        if (tid < NC) {
            float sq = 0.f;
#pragma unroll
            for (int d = 0; d < DC; d++) {
                float v = stot[tid * DC + d];
                sq = fmaf(v, v, sq);
            }
            scl[tid] = sq / ((1.0f + sq) * sqrtf(sq + EPSQ));
        }
        __syncthreads();
        if (p == 1) {
            if (tid < NSLOT) {  // V += v; refresh Vh2
                float sc = scl[tid >> 3];
                float va = Vsm[2 * tid] + sc * stot[2 * tid];
                float vb = Vsm[2 * tid + 1] + sc * stot[2 * tid + 1];
                Vsm[2 * tid] = va;
                Vsm[2 * tid + 1] = vb;
                Vh2[tid] = __floats2half2_rn(va, vb);
            }
            __syncthreads();
        } else {
            if (rank == 0 && tid < JD)
                out[(size_t)b * JD + tid] = scl[tid >> 4] * stot[tid];
        }
        cluster_sync();  // sfin reuse / exit safety
    }
}

// ---------------------------------------------------------------------------
extern "C" void kernel_launch(void* const* d_in, const int* in_sizes, int n_in,
                              void* d_out, int out_size) {
    const float* inputs = (const float*)d_in[0];  // [512, 1152, 8]
    const float* W = (const float*)d_in[1];       // [10, 1152, 16, 8]
    float* out = (float*)d_out;                   // [512, 10, 16]

    uhat_kernel<<<INC, 256>>>(inputs, W);

    const int smem = UBYTES + (RW * JD + 3 * JD) * 4 + NSLOT * 4 + 16 * 4 +
                     IQ * NC * 2 + IQ * 4 + 16;  // ~107 KB (+mbar)
    cudaFuncSetAttribute(route_kernel,
                         cudaFuncAttributeMaxDynamicSharedMemorySize, smem);
    route_kernel<<<BATCH * CSZ, 384, smem>>>(out);
}